// round 5
// baseline (speedup 1.0000x reference)
#include <cuda_runtime.h>
#include <math.h>
#include <cstdint>

#define N_NODES 10000
#define N_EDGES 160000
#define FDIM 128
#define NRBD 32
#define PHI_DIM 1024

// scratch (static device globals: allocation-free)
__device__ float g_h[N_NODES * FDIM];       // silu(s@W1+b1)
__device__ float g_phi[N_NODES * PHI_DIM];  // phi

// ---------------- packed f32x2 helpers (Blackwell FFMA2) ----------------
__device__ __forceinline__ unsigned long long pack2(float lo, float hi) {
    unsigned long long r;
    asm("mov.b64 %0, {%1, %2};" : "=l"(r) : "f"(lo), "f"(hi));
    return r;
}
__device__ __forceinline__ unsigned long long fma2(unsigned long long a,
                                                   unsigned long long b,
                                                   unsigned long long c) {
    unsigned long long d;
    asm("fma.rn.f32x2 %0, %1, %2, %3;" : "=l"(d) : "l"(a), "l"(b), "l"(c));
    return d;
}
__device__ __forceinline__ float2 unpack2(unsigned long long p) {
    float2 f;
    asm("mov.b64 {%0, %1}, %2;" : "=f"(f.x), "=f"(f.y) : "l"(p));
    return f;
}

// ---------------- init: out = concat(s, v) ----------------
__global__ void init_out_kernel(const float* __restrict__ s,
                                const float* __restrict__ v,
                                float* __restrict__ out) {
    int ns4 = (N_NODES * FDIM) / 4;
    int nv4 = (N_NODES * 3 * FDIM) / 4;
    int total4 = ns4 + nv4;
    for (int t = blockIdx.x * blockDim.x + threadIdx.x; t < total4;
         t += gridDim.x * blockDim.x) {
        float4 val = (t < ns4) ? ((const float4*)s)[t]
                               : ((const float4*)v)[t - ns4];
        ((float4*)out)[t] = val;
    }
}

// ---------------- SGEMM: C = A[M,K] @ B[K,N] + bias, optional SiLU ----------
// BM=BN=64, BK=16, TM=TN=4, 256 threads, FFMA2 inner loop.
template <bool SILU>
__global__ __launch_bounds__(256) void sgemm_kernel(
    const float* __restrict__ A, const float* __restrict__ B,
    const float* __restrict__ bias, float* __restrict__ C,
    int M, int N, int K) {
    __shared__ float As[16][68];  // transposed, padded
    __shared__ float Bs[16][64];

    int tid = threadIdx.x;
    int tx = tid % 16, ty = tid / 16;
    int bRow = blockIdx.y * 64, bCol = blockIdx.x * 64;
    int aRow = tid / 4, aCol = (tid % 4) * 4;
    int bRowL = tid / 16, bColL = (tid % 16) * 4;

    unsigned long long accp[4][2];
#pragma unroll
    for (int i = 0; i < 4; i++) {
        accp[i][0] = 0ULL;
        accp[i][1] = 0ULL;
    }

    for (int kt = 0; kt < K; kt += 16) {
        float4 a = make_float4(0.f, 0.f, 0.f, 0.f);
        int gRow = bRow + aRow;
        if (gRow < M) a = *(const float4*)(A + (size_t)gRow * K + kt + aCol);
        As[aCol + 0][aRow] = a.x;
        As[aCol + 1][aRow] = a.y;
        As[aCol + 2][aRow] = a.z;
        As[aCol + 3][aRow] = a.w;

        float4 b = *(const float4*)(B + (size_t)(kt + bRowL) * N + bCol + bColL);
        *(float4*)&Bs[bRowL][bColL] = b;
        __syncthreads();

#pragma unroll
        for (int k = 0; k < 16; ++k) {
            float4 bn = *(float4*)&Bs[k][tx * 4];
            unsigned long long pb0 = pack2(bn.x, bn.y);
            unsigned long long pb1 = pack2(bn.z, bn.w);
#pragma unroll
            for (int i = 0; i < 4; i++) {
                float rm = As[k][ty * 4 + i];
                unsigned long long rd = pack2(rm, rm);
                accp[i][0] = fma2(rd, pb0, accp[i][0]);
                accp[i][1] = fma2(rd, pb1, accp[i][1]);
            }
        }
        __syncthreads();
    }

#pragma unroll
    for (int i = 0; i < 4; i++) {
        int r = bRow + ty * 4 + i;
        if (r >= M) continue;
        float2 p0 = unpack2(accp[i][0]);
        float2 p1 = unpack2(accp[i][1]);
        float vals[4] = {p0.x, p0.y, p1.x, p1.y};
#pragma unroll
        for (int j = 0; j < 4; j++) {
            int c = bCol + tx * 4 + j;
            float val = vals[j] + bias[c];
            if (SILU) val = val / (1.0f + expf(-val));
            C[(size_t)r * N + c] = val;
        }
    }
}

// ---------------- fused edge kernel ----------------
// 1024 threads = 8 eslots x 128 features; each eslot handles 4 edges of a
// 32-edge tile. Wr resident in SMEM (split float4 arrays). Mainloop uses
// packed fma.rn.f32x2. 32 warps/SM for latency hiding of the gather/scatter
// epilogue (LDG ~250cyc L2, REDG ~318cyc).
__global__ __launch_bounds__(1024, 1) void edge_kernel(
    const float* __restrict__ re1, const float* __restrict__ re2,
    const float* __restrict__ re3, const float* __restrict__ fc1,
    const float* __restrict__ fc2, const float* __restrict__ fc3,
    const float* __restrict__ uv1, const float* __restrict__ uv2,
    const float* __restrict__ uv3, const int* __restrict__ eidx,
    const float* __restrict__ Wr, const float* __restrict__ br,
    const float* __restrict__ v, float* __restrict__ out) {
    extern __shared__ float smem[];
    float4* wrA = (float4*)smem;         // [32*128] chunks 0..3
    float4* wrB = wrA + NRBD * FDIM;     // [32*128] chunks 4..7
    float4* rc4 = wrB + NRBD * FDIM;     // [32 edges][8]  (rcomb as float4)
    float* uvs = (float*)(rc4 + 32 * 8); // [32][9]
    float* fcs = uvs + 32 * 9;           // [32]
    int* iis = (int*)(fcs + 32);         // [32]
    int* jjs = iis + 32;                 // [32]

    int tid = threadIdx.x;

    // one-time Wr load into transposed/split SMEM layout
    for (int idx = tid; idx < NRBD * PHI_DIM; idx += 1024) {
        int k = idx >> 10;
        int col = idx & 1023;
        int c = col >> 7, ff = col & 127;
        float val = Wr[idx];
        float* dst = (c < 4) ? (float*)&wrA[k * FDIM + ff]
                             : (float*)&wrB[k * FDIM + ff];
        dst[c & 3] = val;
    }

    int ff = tid & 127;
    int eslot = tid >> 7;  // 0..7

    float brc[8];
#pragma unroll
    for (int c = 0; c < 8; c++) brc[c] = br[c * FDIM + ff];

    float* out_s = out;
    float* out_v = out + (size_t)N_NODES * FDIM;

    const int numTiles = N_EDGES / 32;
    for (int tile = blockIdx.x; tile < numTiles; tile += gridDim.x) {
        __syncthreads();  // protect smem staging vs previous iteration readers
        int eBase = tile * 32;

        // stage rcomb (32 edges x 32 k), float4-vectorized: 256 float4 / tile
        if (tid < 32 * 8) {
            int t = tid;
            int e = t >> 3;
            int ge = eBase + e;
            float c1 = fc1[ge], c2 = fc2[ge], c3 = fc3[ge];
            float4 a = ((const float4*)re1)[ge * 8 + (t & 7)];
            float4 b = ((const float4*)re2)[ge * 8 + (t & 7)];
            float4 c = ((const float4*)re3)[ge * 8 + (t & 7)];
            float4 r;
            r.x = a.x * c1 + b.x * c2 + c.x * c3;
            r.y = a.y * c1 + b.y * c2 + c.y * c3;
            r.z = a.z * c1 + b.z * c2 + c.z * c3;
            r.w = a.w * c1 + b.w * c2 + c.w * c3;
            rc4[t] = r;
        }
        // per-edge metadata
        if (tid >= 512 && tid < 544) {
            int le = tid - 512;
            int ge = eBase + le;
            iis[le] = eidx[ge];
            jjs[le] = eidx[N_EDGES + ge];
            fcs[le] = fc1[ge] + fc2[ge] + fc3[ge];
#pragma unroll
            for (int d = 0; d < 3; d++) {
                uvs[le * 9 + d] = uv1[ge * 3 + d];
                uvs[le * 9 + 3 + d] = uv2[ge * 3 + d];
                uvs[le * 9 + 6 + d] = uv3[ge * 3 + d];
            }
        }
        __syncthreads();

        // W accumulators: 4 edges x 4 chunk-pairs, packed f32x2
        unsigned long long accp[4][4];
#pragma unroll
        for (int e = 0; e < 4; e++) {
            float fs = fcs[eslot * 4 + e];
            accp[e][0] = pack2(fs * brc[0], fs * brc[1]);
            accp[e][1] = pack2(fs * brc[2], fs * brc[3]);
            accp[e][2] = pack2(fs * brc[4], fs * brc[5]);
            accp[e][3] = pack2(fs * brc[6], fs * brc[7]);
        }

#pragma unroll
        for (int kk = 0; kk < 8; ++kk) {
            float4 r[4];
#pragma unroll
            for (int e = 0; e < 4; e++) r[e] = rc4[(eslot * 4 + e) * 8 + kk];
#pragma unroll
            for (int d = 0; d < 4; ++d) {
                int k = kk * 4 + d;
                float4 a = wrA[k * FDIM + ff];
                float4 b = wrB[k * FDIM + ff];
                unsigned long long pa0 = pack2(a.x, a.y);
                unsigned long long pa1 = pack2(a.z, a.w);
                unsigned long long pb0 = pack2(b.x, b.y);
                unsigned long long pb1 = pack2(b.z, b.w);
#pragma unroll
                for (int e = 0; e < 4; e++) {
                    float rv = (d == 0) ? r[e].x
                             : (d == 1) ? r[e].y
                             : (d == 2) ? r[e].z
                                        : r[e].w;
                    unsigned long long rp = pack2(rv, rv);
                    accp[e][0] = fma2(rp, pa0, accp[e][0]);
                    accp[e][1] = fma2(rp, pa1, accp[e][1]);
                    accp[e][2] = fma2(rp, pb0, accp[e][2]);
                    accp[e][3] = fma2(rp, pb1, accp[e][3]);
                }
            }
        }

        // epilogue: gather phi/v, vector + cross math, scatter-add
#pragma unroll
        for (int e = 0; e < 4; e++) {
            int le = eslot * 4 + e;
            int i = iis[le], j = jjs[le];
            float2 p0 = unpack2(accp[e][0]);
            float2 p1 = unpack2(accp[e][1]);
            float2 p2 = unpack2(accp[e][2]);
            float2 p3 = unpack2(accp[e][3]);
            const float* pj = g_phi + (size_t)j * PHI_DIM + ff;
            float x0 = p0.x * pj[0];
            float x1 = p0.y * pj[128];
            float x2 = p1.x * pj[256];
            float x3 = p1.y * pj[384];
            float x4 = p2.x * pj[512];
            float x5 = p2.y * pj[640];
            float x6 = p3.x * pj[768];
            float x7 = p3.y * pj[896];

            const float* vj = v + (size_t)j * (3 * FDIM) + ff;
            float v0 = vj[0], v1 = vj[128], v2 = vj[256];

            float u1x = uvs[le * 9 + 0], u1y = uvs[le * 9 + 1], u1z = uvs[le * 9 + 2];
            float u2x = uvs[le * 9 + 3], u2y = uvs[le * 9 + 4], u2z = uvs[le * 9 + 5];
            float u3x = uvs[le * 9 + 6], u3y = uvs[le * 9 + 7], u3z = uvs[le * 9 + 8];

            // cross(vj, u) = (v1*uz - v2*uy, v2*ux - v0*uz, v0*uy - v1*ux)
            float xv0 = v0 * x1 + x2 * u1x + x3 * u2x + x4 * u3x +
                        x5 * (v1 * u1z - v2 * u1y) +
                        x6 * (v1 * u2z - v2 * u2y) +
                        x7 * (v1 * u3z - v2 * u3y);
            float xv1 = v1 * x1 + x2 * u1y + x3 * u2y + x4 * u3y +
                        x5 * (v2 * u1x - v0 * u1z) +
                        x6 * (v2 * u2x - v0 * u2z) +
                        x7 * (v2 * u3x - v0 * u3z);
            float xv2 = v2 * x1 + x2 * u1z + x3 * u2z + x4 * u3z +
                        x5 * (v0 * u1y - v1 * u1x) +
                        x6 * (v0 * u2y - v1 * u2x) +
                        x7 * (v0 * u3y - v1 * u3x);

            atomicAdd(out_s + (size_t)i * FDIM + ff, x0);
            float* ov = out_v + (size_t)i * (3 * FDIM) + ff;
            atomicAdd(ov, xv0);
            atomicAdd(ov + 128, xv1);
            atomicAdd(ov + 256, xv2);
        }
    }
}

// ---------------- host ----------------
extern "C" void kernel_launch(void* const* d_in, const int* in_sizes, int n_in,
                              void* d_out, int out_size) {
    const float* s = (const float*)d_in[0];
    const float* v = (const float*)d_in[1];
    const float* re1 = (const float*)d_in[2];
    const float* re2 = (const float*)d_in[3];
    const float* re3 = (const float*)d_in[4];
    const float* fc1 = (const float*)d_in[5];
    const float* fc2 = (const float*)d_in[6];
    const float* fc3 = (const float*)d_in[7];
    const float* uv1 = (const float*)d_in[8];
    const float* uv2 = (const float*)d_in[9];
    const float* uv3 = (const float*)d_in[10];
    const int* eidx = (const int*)d_in[11];
    const float* W1 = (const float*)d_in[12];
    const float* b1 = (const float*)d_in[13];
    const float* W2 = (const float*)d_in[14];
    const float* b2 = (const float*)d_in[15];
    const float* Wr = (const float*)d_in[16];
    const float* br = (const float*)d_in[17];
    float* out = (float*)d_out;

    float *hptr, *phiptr;
    cudaGetSymbolAddress((void**)&hptr, g_h);
    cudaGetSymbolAddress((void**)&phiptr, g_phi);

    init_out_kernel<<<256, 256>>>(s, v, out);

    dim3 g1(FDIM / 64, (N_NODES + 63) / 64);
    sgemm_kernel<true><<<g1, 256>>>(s, W1, b1, hptr, N_NODES, FDIM, FDIM);

    dim3 g2(PHI_DIM / 64, (N_NODES + 63) / 64);
    sgemm_kernel<false><<<g2, 256>>>(hptr, W2, b2, phiptr, N_NODES, PHI_DIM, FDIM);

    int smem_bytes = (NRBD * FDIM * 2 + 32 * 8) * (int)sizeof(float4) +
                     (32 * 9 + 32) * (int)sizeof(float) + 32 * 2 * (int)sizeof(int);
    cudaFuncSetAttribute(edge_kernel,
                         cudaFuncAttributeMaxDynamicSharedMemorySize, smem_bytes);
    edge_kernel<<<148, 1024, smem_bytes>>>(re1, re2, re3, fc1, fc2, fc3, uv1, uv2,
                                           uv3, eidx, Wr, br, v, out);
}

// round 6
// speedup vs baseline: 1.4201x; 1.4201x over previous
#include <cuda_runtime.h>
#include <math.h>
#include <cstdint>

#define N_NODES 10000
#define N_EDGES 160000
#define FDIM 128
#define NRBD 32
#define PHI_DIM 1024

// scratch (static device globals: allocation-free)
__device__ float g_h[N_NODES * FDIM];       // silu(s@W1+b1)
__device__ float g_phi[N_NODES * PHI_DIM];  // phi

// ---------------- packed f32x2 helpers (Blackwell FFMA2) ----------------
__device__ __forceinline__ unsigned long long pack2(float lo, float hi) {
    unsigned long long r;
    asm("mov.b64 %0, {%1, %2};" : "=l"(r) : "f"(lo), "f"(hi));
    return r;
}
__device__ __forceinline__ unsigned long long fma2(unsigned long long a,
                                                   unsigned long long b,
                                                   unsigned long long c) {
    unsigned long long d;
    asm("fma.rn.f32x2 %0, %1, %2, %3;" : "=l"(d) : "l"(a), "l"(b), "l"(c));
    return d;
}
__device__ __forceinline__ float2 unpack2(unsigned long long p) {
    float2 f;
    asm("mov.b64 {%0, %1}, %2;" : "=f"(f.x), "=f"(f.y) : "l"(p));
    return f;
}

// ---------------- init: out = concat(s, v) ----------------
__global__ void init_out_kernel(const float* __restrict__ s,
                                const float* __restrict__ v,
                                float* __restrict__ out) {
    int ns4 = (N_NODES * FDIM) / 4;
    int nv4 = (N_NODES * 3 * FDIM) / 4;
    int total4 = ns4 + nv4;
    for (int t = blockIdx.x * blockDim.x + threadIdx.x; t < total4;
         t += gridDim.x * blockDim.x) {
        float4 val = (t < ns4) ? ((const float4*)s)[t]
                               : ((const float4*)v)[t - ns4];
        ((float4*)out)[t] = val;
    }
}

// ---------------- SGEMM: C = A[M,K] @ B[K,N] + bias, optional SiLU ----------
// BM=BN=64, BK=16, TM=TN=4, 256 threads, FFMA2 inner loop.
template <bool SILU>
__global__ __launch_bounds__(256) void sgemm_kernel(
    const float* __restrict__ A, const float* __restrict__ B,
    const float* __restrict__ bias, float* __restrict__ C,
    int M, int N, int K) {
    __shared__ float As[16][68];  // transposed, padded
    __shared__ float Bs[16][64];

    int tid = threadIdx.x;
    int tx = tid % 16, ty = tid / 16;
    int bRow = blockIdx.y * 64, bCol = blockIdx.x * 64;
    int aRow = tid / 4, aCol = (tid % 4) * 4;
    int bRowL = tid / 16, bColL = (tid % 16) * 4;

    unsigned long long accp[4][2];
#pragma unroll
    for (int i = 0; i < 4; i++) {
        accp[i][0] = 0ULL;
        accp[i][1] = 0ULL;
    }

    for (int kt = 0; kt < K; kt += 16) {
        float4 a = make_float4(0.f, 0.f, 0.f, 0.f);
        int gRow = bRow + aRow;
        if (gRow < M) a = *(const float4*)(A + (size_t)gRow * K + kt + aCol);
        As[aCol + 0][aRow] = a.x;
        As[aCol + 1][aRow] = a.y;
        As[aCol + 2][aRow] = a.z;
        As[aCol + 3][aRow] = a.w;

        float4 b = *(const float4*)(B + (size_t)(kt + bRowL) * N + bCol + bColL);
        *(float4*)&Bs[bRowL][bColL] = b;
        __syncthreads();

#pragma unroll
        for (int k = 0; k < 16; ++k) {
            float4 bn = *(float4*)&Bs[k][tx * 4];
            unsigned long long pb0 = pack2(bn.x, bn.y);
            unsigned long long pb1 = pack2(bn.z, bn.w);
#pragma unroll
            for (int i = 0; i < 4; i++) {
                float rm = As[k][ty * 4 + i];
                unsigned long long rd = pack2(rm, rm);
                accp[i][0] = fma2(rd, pb0, accp[i][0]);
                accp[i][1] = fma2(rd, pb1, accp[i][1]);
            }
        }
        __syncthreads();
    }

#pragma unroll
    for (int i = 0; i < 4; i++) {
        int r = bRow + ty * 4 + i;
        if (r >= M) continue;
        float2 p0 = unpack2(accp[i][0]);
        float2 p1 = unpack2(accp[i][1]);
        float vals[4] = {p0.x, p0.y, p1.x, p1.y};
#pragma unroll
        for (int j = 0; j < 4; j++) {
            int c = bCol + tx * 4 + j;
            float val = vals[j] + bias[c];
            if (SILU) val = val / (1.0f + expf(-val));
            C[(size_t)r * N + c] = val;
        }
    }
}

// ---------------- fused edge kernel (k-outer, edge-paired FFMA2) -----------
// 512 threads = 128 ff x 4 chunk-pair slots. Tile = 32 edges.
// Slot s owns chunks {2s, 2s+1}. Mainloop is k-outer: per k, each thread
// loads 2 Wr scalars (dup'd once) and FMAs them against all 16 edge-pairs
// (rcomb staged transposed [k][e] so pairs load as native u64 -> no packing).
// Epilogue exchanges x through a double-buffered smem tile (4 rounds of 8
// edges), then per-edge vector/cross math + scatter atomics.
__global__ __launch_bounds__(512, 1) void edge_kernel(
    const float* __restrict__ re1, const float* __restrict__ re2,
    const float* __restrict__ re3, const float* __restrict__ fc1,
    const float* __restrict__ fc2, const float* __restrict__ fc3,
    const float* __restrict__ uv1, const float* __restrict__ uv2,
    const float* __restrict__ uv3, const int* __restrict__ eidx,
    const float* __restrict__ Wr, const float* __restrict__ br,
    const float* __restrict__ v, float* __restrict__ out) {
    extern __shared__ float smem[];
    float* wrS = smem;                   // [32][1024] straight copy of Wr
    float* rcS = wrS + NRBD * PHI_DIM;   // [32 k][32 e] rcomb transposed
    float* xS = rcS + NRBD * 32;         // [2][8 e][8 c][128 ff] = 16384 floats
    float* uvs = xS + 2 * 8 * PHI_DIM;   // [32][9]
    float* fcs = uvs + 32 * 9;           // [32]
    int* iis = (int*)(fcs + 32);         // [32]
    int* jjs = iis + 32;                 // [32]

    int tid = threadIdx.x;
    int ff = tid & 127;
    int slot = tid >> 7;  // 0..3
    int c0 = 2 * slot, c1 = c0 + 1;

    // one-time: copy Wr straight into smem (layout identical)
    for (int i = tid; i < NRBD * PHI_DIM / 4; i += 512)
        ((float4*)wrS)[i] = ((const float4*)Wr)[i];

    float br0 = br[c0 * FDIM + ff];
    float br1 = br[c1 * FDIM + ff];

    float* out_s = out;
    float* out_v = out + (size_t)N_NODES * FDIM;

    const int numTiles = N_EDGES / 32;
    for (int tile = blockIdx.x; tile < numTiles; tile += gridDim.x) {
        __syncthreads();  // staging vs previous tile's readers
        int eBase = tile * 32;

        // stage rcomb transposed: thread t = kq*32 + e (t < 256)
        if (tid < 256) {
            int kq = tid >> 5, e = tid & 31;
            int ge = eBase + e;
            float cA = fc1[ge], cB = fc2[ge], cC = fc3[ge];
            float4 a = ((const float4*)re1)[ge * 8 + kq];
            float4 b = ((const float4*)re2)[ge * 8 + kq];
            float4 c = ((const float4*)re3)[ge * 8 + kq];
            rcS[(4 * kq + 0) * 32 + e] = a.x * cA + b.x * cB + c.x * cC;
            rcS[(4 * kq + 1) * 32 + e] = a.y * cA + b.y * cB + c.y * cC;
            rcS[(4 * kq + 2) * 32 + e] = a.z * cA + b.z * cB + c.z * cC;
            rcS[(4 * kq + 3) * 32 + e] = a.w * cA + b.w * cB + c.w * cC;
        } else if (tid < 288) {
            int le = tid - 256;
            int ge = eBase + le;
            iis[le] = eidx[ge];
            jjs[le] = eidx[N_EDGES + ge];
            fcs[le] = fc1[ge] + fc2[ge] + fc3[ge];
#pragma unroll
            for (int d = 0; d < 3; d++) {
                uvs[le * 9 + d] = uv1[ge * 3 + d];
                uvs[le * 9 + 3 + d] = uv2[ge * 3 + d];
                uvs[le * 9 + 6 + d] = uv3[ge * 3 + d];
            }
        }
        __syncthreads();

        // acc[ep][c]: pair = (edge 2ep, edge 2ep+1) for chunk c in {c0,c1}
        unsigned long long acc[16][2];
#pragma unroll
        for (int ep = 0; ep < 16; ep++) {
            float f0 = fcs[2 * ep], f1 = fcs[2 * ep + 1];
            acc[ep][0] = pack2(f0 * br0, f1 * br0);
            acc[ep][1] = pack2(f0 * br1, f1 * br1);
        }

        // mainloop: k outer, all 32 edges inner
#pragma unroll 4
        for (int k = 0; k < NRBD; ++k) {
            float w0 = wrS[k * PHI_DIM + c0 * FDIM + ff];
            float w1 = wrS[k * PHI_DIM + c1 * FDIM + ff];
            unsigned long long wd0 = pack2(w0, w0);
            unsigned long long wd1 = pack2(w1, w1);
            const ulonglong2* rp4 = (const ulonglong2*)&rcS[k * 32];
#pragma unroll
            for (int p = 0; p < 8; p++) {
                ulonglong2 rr = rp4[p];  // 2 edge-pairs
                acc[2 * p + 0][0] = fma2(rr.x, wd0, acc[2 * p + 0][0]);
                acc[2 * p + 0][1] = fma2(rr.x, wd1, acc[2 * p + 0][1]);
                acc[2 * p + 1][0] = fma2(rr.y, wd0, acc[2 * p + 1][0]);
                acc[2 * p + 1][1] = fma2(rr.y, wd1, acc[2 * p + 1][1]);
            }
        }

        // epilogue: 4 rounds of 8 edges, double-buffered x exchange
#pragma unroll
        for (int g = 0; g < 4; g++) {
            float* xb = xS + (g & 1) * (8 * PHI_DIM);

            // write phase: x = acc * phi[j] for this thread's 2 chunks
            float pv[16];
#pragma unroll
            for (int pp = 0; pp < 4; pp++) {
                int e0 = 2 * pp, e1 = 2 * pp + 1;  // local e8 within round
                int j0 = jjs[g * 8 + e0], j1 = jjs[g * 8 + e1];
                const float* p0 = g_phi + (size_t)j0 * PHI_DIM + ff;
                const float* p1 = g_phi + (size_t)j1 * PHI_DIM + ff;
                pv[pp * 4 + 0] = p0[c0 * FDIM];
                pv[pp * 4 + 1] = p1[c0 * FDIM];
                pv[pp * 4 + 2] = p0[c1 * FDIM];
                pv[pp * 4 + 3] = p1[c1 * FDIM];
            }
#pragma unroll
            for (int pp = 0; pp < 4; pp++) {
                int ep = g * 4 + pp;
                int e0 = 2 * pp, e1 = 2 * pp + 1;
                float2 a0 = unpack2(acc[ep][0]);
                float2 a1 = unpack2(acc[ep][1]);
                xb[e0 * PHI_DIM + c0 * FDIM + ff] = a0.x * pv[pp * 4 + 0];
                xb[e1 * PHI_DIM + c0 * FDIM + ff] = a0.y * pv[pp * 4 + 1];
                xb[e0 * PHI_DIM + c1 * FDIM + ff] = a1.x * pv[pp * 4 + 2];
                xb[e1 * PHI_DIM + c1 * FDIM + ff] = a1.y * pv[pp * 4 + 3];
            }
            __syncthreads();

            // vector phase: this thread handles edges g*8 + 2*slot + {0,1}
#pragma unroll
            for (int q = 0; q < 2; q++) {
                int e8 = 2 * slot + q;
                int le = g * 8 + e8;
                int i = iis[le], j = jjs[le];
                const float* xe = xb + e8 * PHI_DIM + ff;
                float x0 = xe[0 * FDIM];
                float x1 = xe[1 * FDIM];
                float x2 = xe[2 * FDIM];
                float x3 = xe[3 * FDIM];
                float x4 = xe[4 * FDIM];
                float x5 = xe[5 * FDIM];
                float x6 = xe[6 * FDIM];
                float x7 = xe[7 * FDIM];

                const float* vj = v + (size_t)j * (3 * FDIM) + ff;
                float v0 = vj[0], v1 = vj[128], v2 = vj[256];

                float u1x = uvs[le * 9 + 0], u1y = uvs[le * 9 + 1],
                      u1z = uvs[le * 9 + 2];
                float u2x = uvs[le * 9 + 3], u2y = uvs[le * 9 + 4],
                      u2z = uvs[le * 9 + 5];
                float u3x = uvs[le * 9 + 6], u3y = uvs[le * 9 + 7],
                      u3z = uvs[le * 9 + 8];

                // cross(vj,u) = (v1*uz - v2*uy, v2*ux - v0*uz, v0*uy - v1*ux)
                float xv0 = v0 * x1 + x2 * u1x + x3 * u2x + x4 * u3x +
                            x5 * (v1 * u1z - v2 * u1y) +
                            x6 * (v1 * u2z - v2 * u2y) +
                            x7 * (v1 * u3z - v2 * u3y);
                float xv1 = v1 * x1 + x2 * u1y + x3 * u2y + x4 * u3y +
                            x5 * (v2 * u1x - v0 * u1z) +
                            x6 * (v2 * u2x - v0 * u2z) +
                            x7 * (v2 * u3x - v0 * u3z);
                float xv2 = v2 * x1 + x2 * u1z + x3 * u2z + x4 * u3z +
                            x5 * (v0 * u1y - v1 * u1x) +
                            x6 * (v0 * u2y - v1 * u2x) +
                            x7 * (v0 * u3y - v1 * u3x);

                atomicAdd(out_s + (size_t)i * FDIM + ff, x0);
                float* ov = out_v + (size_t)i * (3 * FDIM) + ff;
                atomicAdd(ov, xv0);
                atomicAdd(ov + 128, xv1);
                atomicAdd(ov + 256, xv2);
            }
            // no trailing sync: next round writes the other x buffer; a
            // buffer is only rewritten after the sync two rounds later.
        }
    }
}

// ---------------- host ----------------
extern "C" void kernel_launch(void* const* d_in, const int* in_sizes, int n_in,
                              void* d_out, int out_size) {
    const float* s = (const float*)d_in[0];
    const float* v = (const float*)d_in[1];
    const float* re1 = (const float*)d_in[2];
    const float* re2 = (const float*)d_in[3];
    const float* re3 = (const float*)d_in[4];
    const float* fc1 = (const float*)d_in[5];
    const float* fc2 = (const float*)d_in[6];
    const float* fc3 = (const float*)d_in[7];
    const float* uv1 = (const float*)d_in[8];
    const float* uv2 = (const float*)d_in[9];
    const float* uv3 = (const float*)d_in[10];
    const int* eidx = (const int*)d_in[11];
    const float* W1 = (const float*)d_in[12];
    const float* b1 = (const float*)d_in[13];
    const float* W2 = (const float*)d_in[14];
    const float* b2 = (const float*)d_in[15];
    const float* Wr = (const float*)d_in[16];
    const float* br = (const float*)d_in[17];
    float* out = (float*)d_out;

    float *hptr, *phiptr;
    cudaGetSymbolAddress((void**)&hptr, g_h);
    cudaGetSymbolAddress((void**)&phiptr, g_phi);

    init_out_kernel<<<256, 256>>>(s, v, out);

    dim3 g1(FDIM / 64, (N_NODES + 63) / 64);
    sgemm_kernel<true><<<g1, 256>>>(s, W1, b1, hptr, N_NODES, FDIM, FDIM);

    dim3 g2(PHI_DIM / 64, (N_NODES + 63) / 64);
    sgemm_kernel<false><<<g2, 256>>>(hptr, W2, b2, phiptr, N_NODES, PHI_DIM, FDIM);

    int smem_floats = NRBD * PHI_DIM      // wrS
                      + NRBD * 32         // rcS
                      + 2 * 8 * PHI_DIM   // xS (double buffered)
                      + 32 * 9 + 32;      // uvs + fcs
    int smem_bytes = smem_floats * (int)sizeof(float) + 32 * 2 * (int)sizeof(int);
    cudaFuncSetAttribute(edge_kernel,
                         cudaFuncAttributeMaxDynamicSharedMemorySize, smem_bytes);
    edge_kernel<<<148, 512, smem_bytes>>>(re1, re2, re3, fc1, fc2, fc3, uv1, uv2,
                                          uv3, eidx, Wr, br, v, out);
}

// round 7
// speedup vs baseline: 1.9523x; 1.3748x over previous
#include <cuda_runtime.h>
#include <math.h>
#include <cstdint>

#define N_NODES 10000
#define N_EDGES 160000
#define FDIM 128
#define NRBD 32
#define PHI_DIM 1024

// scratch (static device globals: allocation-free)
__device__ float g_h[N_NODES * FDIM];       // silu(s@W1+b1)
__device__ float g_phi[N_NODES * PHI_DIM];  // phi

// ---------------- packed f32x2 helpers (Blackwell FFMA2) ----------------
__device__ __forceinline__ unsigned long long pack2(float lo, float hi) {
    unsigned long long r;
    asm("mov.b64 %0, {%1, %2};" : "=l"(r) : "f"(lo), "f"(hi));
    return r;
}
__device__ __forceinline__ unsigned long long fma2(unsigned long long a,
                                                   unsigned long long b,
                                                   unsigned long long c) {
    unsigned long long d;
    asm("fma.rn.f32x2 %0, %1, %2, %3;" : "=l"(d) : "l"(a), "l"(b), "l"(c));
    return d;
}
__device__ __forceinline__ float2 unpack2(unsigned long long p) {
    float2 f;
    asm("mov.b64 {%0, %1}, %2;" : "=f"(f.x), "=f"(f.y) : "l"(p));
    return f;
}

// ---------------- init: out = concat(s, v) ----------------
__global__ void init_out_kernel(const float* __restrict__ s,
                                const float* __restrict__ v,
                                float* __restrict__ out) {
    int ns4 = (N_NODES * FDIM) / 4;
    int nv4 = (N_NODES * 3 * FDIM) / 4;
    int total4 = ns4 + nv4;
    for (int t = blockIdx.x * blockDim.x + threadIdx.x; t < total4;
         t += gridDim.x * blockDim.x) {
        float4 val = (t < ns4) ? ((const float4*)s)[t]
                               : ((const float4*)v)[t - ns4];
        ((float4*)out)[t] = val;
    }
}

// ---------------- SGEMM: C = A[M,K] @ B[K,N] + bias, optional SiLU ----------
// BM=128, BN=64, BK=16, TM=8, TN=4, 256 threads, FFMA2 inner loop.
template <bool SILU>
__global__ __launch_bounds__(256) void sgemm_kernel(
    const float* __restrict__ A, const float* __restrict__ B,
    const float* __restrict__ bias, float* __restrict__ C,
    int M, int N, int K) {
    __shared__ float As[16][132];  // transposed, padded
    __shared__ float Bs[16][64];

    int tid = threadIdx.x;
    int tx = tid % 16, ty = tid / 16;  // ty 0..15 -> 8 rows each
    int bRow = blockIdx.y * 128, bCol = blockIdx.x * 64;
    int bRowL = tid / 16, bColL = (tid % 16) * 4;

    unsigned long long accp[8][2];
#pragma unroll
    for (int i = 0; i < 8; i++) {
        accp[i][0] = 0ULL;
        accp[i][1] = 0ULL;
    }

    for (int kt = 0; kt < K; kt += 16) {
        // A tile: 128 rows x 16 cols = 512 float4; 2 per thread
#pragma unroll
        for (int l = 0; l < 2; l++) {
            int idx = tid + l * 256;
            int row = idx >> 2, c4 = (idx & 3) * 4;
            float4 a = make_float4(0.f, 0.f, 0.f, 0.f);
            int gRow = bRow + row;
            if (gRow < M) a = *(const float4*)(A + (size_t)gRow * K + kt + c4);
            As[c4 + 0][row] = a.x;
            As[c4 + 1][row] = a.y;
            As[c4 + 2][row] = a.z;
            As[c4 + 3][row] = a.w;
        }
        float4 b = *(const float4*)(B + (size_t)(kt + bRowL) * N + bCol + bColL);
        *(float4*)&Bs[bRowL][bColL] = b;
        __syncthreads();

#pragma unroll
        for (int k = 0; k < 16; ++k) {
            float4 bn = *(float4*)&Bs[k][tx * 4];
            unsigned long long pb0 = pack2(bn.x, bn.y);
            unsigned long long pb1 = pack2(bn.z, bn.w);
#pragma unroll
            for (int i = 0; i < 8; i++) {
                float rm = As[k][ty * 8 + i];
                unsigned long long rd = pack2(rm, rm);
                accp[i][0] = fma2(rd, pb0, accp[i][0]);
                accp[i][1] = fma2(rd, pb1, accp[i][1]);
            }
        }
        __syncthreads();
    }

#pragma unroll
    for (int i = 0; i < 8; i++) {
        int r = bRow + ty * 8 + i;
        if (r >= M) continue;
        float2 p0 = unpack2(accp[i][0]);
        float2 p1 = unpack2(accp[i][1]);
        float vals[4] = {p0.x, p0.y, p1.x, p1.y};
#pragma unroll
        for (int j = 0; j < 4; j++) {
            int c = bCol + tx * 4 + j;
            float val = vals[j] + bias[c];
            if (SILU) val = val / (1.0f + expf(-val));
            C[(size_t)r * N + c] = val;
        }
    }
}

// ---------------- fused edge kernel (R3 structure + micro-opts) -----------
// 512 threads = 4 eslots x 128 features; each eslot register-blocks 8 edges
// of a 32-edge tile. Wr resident in SMEM as two float4 arrays (chunks 0-3 /
// 4-7); mainloop loads them as ulonglong2 (native chunk-pairs, zero packing)
// and uses fma.rn.f32x2. Epilogue processes edges in pairs with all global
// loads hoisted ahead of the math (MLP ~22) via __ldg.
__global__ __launch_bounds__(512, 1) void edge_kernel(
    const float* __restrict__ re1, const float* __restrict__ re2,
    const float* __restrict__ re3, const float* __restrict__ fc1,
    const float* __restrict__ fc2, const float* __restrict__ fc3,
    const float* __restrict__ uv1, const float* __restrict__ uv2,
    const float* __restrict__ uv3, const int* __restrict__ eidx,
    const float* __restrict__ Wr, const float* __restrict__ br,
    const float* __restrict__ v, float* __restrict__ out) {
    extern __shared__ float smem[];
    float4* wrA = (float4*)smem;         // [32*128] chunks 0..3
    float4* wrB = wrA + NRBD * FDIM;     // [32*128] chunks 4..7
    float4* rc4 = wrB + NRBD * FDIM;     // [32 edges][8]  (rcomb as float4)
    float* uvs = (float*)(rc4 + 32 * 8); // [32][9]
    float* fcs = uvs + 32 * 9;           // [32]
    int* iis = (int*)(fcs + 32);         // [32]
    int* jjs = iis + 32;                 // [32]

    int tid = threadIdx.x;

    // one-time Wr load into transposed/split SMEM layout
    for (int idx = tid; idx < NRBD * PHI_DIM; idx += 512) {
        int k = idx >> 10;
        int col = idx & 1023;
        int c = col >> 7, ff = col & 127;
        float val = Wr[idx];
        float* dst = (c < 4) ? (float*)&wrA[k * FDIM + ff]
                             : (float*)&wrB[k * FDIM + ff];
        dst[c & 3] = val;
    }

    int ff = tid & 127;
    int eslot = tid >> 7;

    float brc[8];
#pragma unroll
    for (int c = 0; c < 8; c++) brc[c] = br[c * FDIM + ff];

    float* out_s = out;
    float* out_v = out + (size_t)N_NODES * FDIM;

    const int numTiles = N_EDGES / 32;
    for (int tile = blockIdx.x; tile < numTiles; tile += gridDim.x) {
        __syncthreads();  // protect smem staging vs previous iteration readers
        int eBase = tile * 32;

        // stage rcomb (32 edges x 32 k), float4-vectorized: 256 float4 / tile
        if (tid < 32 * 8) {
            int t = tid;
            int e = t >> 3;
            int ge = eBase + e;
            float c1 = fc1[ge], c2 = fc2[ge], c3 = fc3[ge];
            float4 a = ((const float4*)re1)[ge * 8 + (t & 7)];
            float4 b = ((const float4*)re2)[ge * 8 + (t & 7)];
            float4 c = ((const float4*)re3)[ge * 8 + (t & 7)];
            float4 r;
            r.x = a.x * c1 + b.x * c2 + c.x * c3;
            r.y = a.y * c1 + b.y * c2 + c.y * c3;
            r.z = a.z * c1 + b.z * c2 + c.z * c3;
            r.w = a.w * c1 + b.w * c2 + c.w * c3;
            rc4[t] = r;
        } else if (tid >= 256 && tid < 288) {
            int le = tid - 256;
            int ge = eBase + le;
            iis[le] = eidx[ge];
            jjs[le] = eidx[N_EDGES + ge];
            fcs[le] = fc1[ge] + fc2[ge] + fc3[ge];
#pragma unroll
            for (int d = 0; d < 3; d++) {
                uvs[le * 9 + d] = uv1[ge * 3 + d];
                uvs[le * 9 + 3 + d] = uv2[ge * 3 + d];
                uvs[le * 9 + 6 + d] = uv3[ge * 3 + d];
            }
        }
        __syncthreads();

        // W accumulators: 8 edges x 4 chunk-pairs, packed f32x2
        unsigned long long accp[8][4];
#pragma unroll
        for (int e = 0; e < 8; e++) {
            float fs = fcs[eslot * 8 + e];
            accp[e][0] = pack2(fs * brc[0], fs * brc[1]);
            accp[e][1] = pack2(fs * brc[2], fs * brc[3]);
            accp[e][2] = pack2(fs * brc[4], fs * brc[5]);
            accp[e][3] = pack2(fs * brc[6], fs * brc[7]);
        }

#pragma unroll
        for (int kk = 0; kk < 8; ++kk) {
            float4 r[8];
#pragma unroll
            for (int e = 0; e < 8; e++) r[e] = rc4[(eslot * 8 + e) * 8 + kk];
#pragma unroll
            for (int d = 0; d < 4; ++d) {
                int k = kk * 4 + d;
                // chunk-pairs load natively as u64 halves of the float4
                ulonglong2 wa = *(const ulonglong2*)&wrA[k * FDIM + ff];
                ulonglong2 wb = *(const ulonglong2*)&wrB[k * FDIM + ff];
#pragma unroll
                for (int e = 0; e < 8; e++) {
                    float rv = (d == 0) ? r[e].x
                             : (d == 1) ? r[e].y
                             : (d == 2) ? r[e].z
                                        : r[e].w;
                    unsigned long long rp = pack2(rv, rv);
                    accp[e][0] = fma2(rp, wa.x, accp[e][0]);
                    accp[e][1] = fma2(rp, wa.y, accp[e][1]);
                    accp[e][2] = fma2(rp, wb.x, accp[e][2]);
                    accp[e][3] = fma2(rp, wb.y, accp[e][3]);
                }
            }
        }

        // epilogue: pairs of edges; hoist all global loads before the math
#pragma unroll
        for (int pp = 0; pp < 4; pp++) {
            int le0 = eslot * 8 + 2 * pp;
            int le1 = le0 + 1;
            int i0 = iis[le0], j0 = jjs[le0];
            int i1 = iis[le1], j1 = jjs[le1];

            const float* pj0 = g_phi + (size_t)j0 * PHI_DIM + ff;
            const float* pj1 = g_phi + (size_t)j1 * PHI_DIM + ff;
            const float* vj0 = v + (size_t)j0 * (3 * FDIM) + ff;
            const float* vj1 = v + (size_t)j1 * (3 * FDIM) + ff;

            float ph0[8], ph1[8];
#pragma unroll
            for (int c = 0; c < 8; c++) ph0[c] = __ldg(pj0 + c * FDIM);
#pragma unroll
            for (int c = 0; c < 8; c++) ph1[c] = __ldg(pj1 + c * FDIM);
            float va0 = __ldg(vj0), vb0 = __ldg(vj0 + 128), vc0 = __ldg(vj0 + 256);
            float va1 = __ldg(vj1), vb1 = __ldg(vj1 + 128), vc1 = __ldg(vj1 + 256);

#pragma unroll
            for (int q = 0; q < 2; q++) {
                int le = q ? le1 : le0;
                int i = q ? i1 : i0;
                const float* ph = q ? ph1 : ph0;
                float v0 = q ? va1 : va0;
                float v1 = q ? vb1 : vb0;
                float v2 = q ? vc1 : vc0;
                int eloc = le - eslot * 8;
                float2 p0 = unpack2(accp[eloc][0]);
                float2 p1 = unpack2(accp[eloc][1]);
                float2 p2 = unpack2(accp[eloc][2]);
                float2 p3 = unpack2(accp[eloc][3]);
                float x0 = p0.x * ph[0];
                float x1 = p0.y * ph[1];
                float x2 = p1.x * ph[2];
                float x3 = p1.y * ph[3];
                float x4 = p2.x * ph[4];
                float x5 = p2.y * ph[5];
                float x6 = p3.x * ph[6];
                float x7 = p3.y * ph[7];

                float u1x = uvs[le * 9 + 0], u1y = uvs[le * 9 + 1],
                      u1z = uvs[le * 9 + 2];
                float u2x = uvs[le * 9 + 3], u2y = uvs[le * 9 + 4],
                      u2z = uvs[le * 9 + 5];
                float u3x = uvs[le * 9 + 6], u3y = uvs[le * 9 + 7],
                      u3z = uvs[le * 9 + 8];

                // cross(vj,u) = (v1*uz - v2*uy, v2*ux - v0*uz, v0*uy - v1*ux)
                float xv0 = v0 * x1 + x2 * u1x + x3 * u2x + x4 * u3x +
                            x5 * (v1 * u1z - v2 * u1y) +
                            x6 * (v1 * u2z - v2 * u2y) +
                            x7 * (v1 * u3z - v2 * u3y);
                float xv1 = v1 * x1 + x2 * u1y + x3 * u2y + x4 * u3y +
                            x5 * (v2 * u1x - v0 * u1z) +
                            x6 * (v2 * u2x - v0 * u2z) +
                            x7 * (v2 * u3x - v0 * u3z);
                float xv2 = v2 * x1 + x2 * u1z + x3 * u2z + x4 * u3z +
                            x5 * (v0 * u1y - v1 * u1x) +
                            x6 * (v0 * u2y - v1 * u2x) +
                            x7 * (v0 * u3y - v1 * u3x);

                atomicAdd(out_s + (size_t)i * FDIM + ff, x0);
                float* ov = out_v + (size_t)i * (3 * FDIM) + ff;
                atomicAdd(ov, xv0);
                atomicAdd(ov + 128, xv1);
                atomicAdd(ov + 256, xv2);
            }
        }
    }
}

// ---------------- host ----------------
extern "C" void kernel_launch(void* const* d_in, const int* in_sizes, int n_in,
                              void* d_out, int out_size) {
    const float* s = (const float*)d_in[0];
    const float* v = (const float*)d_in[1];
    const float* re1 = (const float*)d_in[2];
    const float* re2 = (const float*)d_in[3];
    const float* re3 = (const float*)d_in[4];
    const float* fc1 = (const float*)d_in[5];
    const float* fc2 = (const float*)d_in[6];
    const float* fc3 = (const float*)d_in[7];
    const float* uv1 = (const float*)d_in[8];
    const float* uv2 = (const float*)d_in[9];
    const float* uv3 = (const float*)d_in[10];
    const int* eidx = (const int*)d_in[11];
    const float* W1 = (const float*)d_in[12];
    const float* b1 = (const float*)d_in[13];
    const float* W2 = (const float*)d_in[14];
    const float* b2 = (const float*)d_in[15];
    const float* Wr = (const float*)d_in[16];
    const float* br = (const float*)d_in[17];
    float* out = (float*)d_out;

    float *hptr, *phiptr;
    cudaGetSymbolAddress((void**)&hptr, g_h);
    cudaGetSymbolAddress((void**)&phiptr, g_phi);

    init_out_kernel<<<256, 256>>>(s, v, out);

    dim3 g1(FDIM / 64, (N_NODES + 127) / 128);
    sgemm_kernel<true><<<g1, 256>>>(s, W1, b1, hptr, N_NODES, FDIM, FDIM);

    dim3 g2(PHI_DIM / 64, (N_NODES + 127) / 128);
    sgemm_kernel<false><<<g2, 256>>>(hptr, W2, b2, phiptr, N_NODES, PHI_DIM, FDIM);

    int smem_bytes = (NRBD * FDIM * 2 + 32 * 8) * (int)sizeof(float4) +
                     (32 * 9 + 32) * (int)sizeof(float) + 32 * 2 * (int)sizeof(int);
    cudaFuncSetAttribute(edge_kernel,
                         cudaFuncAttributeMaxDynamicSharedMemorySize, smem_bytes);
    edge_kernel<<<148, 512, smem_bytes>>>(re1, re2, re3, fc1, fc2, fc3, uv1, uv2,
                                          uv3, eidx, Wr, br, v, out);
}

// round 9
// speedup vs baseline: 2.0301x; 1.0398x over previous
#include <cuda_runtime.h>
#include <math.h>
#include <cstdint>

#define N_NODES 10000
#define N_EDGES 160000
#define FDIM 128
#define NRBD 32
#define PHI_DIM 1024

// scratch (static device globals: allocation-free)
__device__ float g_h[N_NODES * FDIM];       // silu(s@W1+b1)
__device__ float g_phi[N_NODES * PHI_DIM];  // phi

// ---------------- packed f32x2 helpers (Blackwell FFMA2) ----------------
__device__ __forceinline__ unsigned long long pack2(float lo, float hi) {
    unsigned long long r;
    asm("mov.b64 %0, {%1, %2};" : "=l"(r) : "f"(lo), "f"(hi));
    return r;
}
__device__ __forceinline__ unsigned long long fma2(unsigned long long a,
                                                   unsigned long long b,
                                                   unsigned long long c) {
    unsigned long long d;
    asm("fma.rn.f32x2 %0, %1, %2, %3;" : "=l"(d) : "l"(a), "l"(b), "l"(c));
    return d;
}
__device__ __forceinline__ float2 unpack2(unsigned long long p) {
    float2 f;
    asm("mov.b64 {%0, %1}, %2;" : "=f"(f.x), "=f"(f.y) : "l"(p));
    return f;
}

// ---------------- init: out = concat(s, v) ----------------
__global__ void init_out_kernel(const float* __restrict__ s,
                                const float* __restrict__ v,
                                float* __restrict__ out) {
    int ns4 = (N_NODES * FDIM) / 4;
    int nv4 = (N_NODES * 3 * FDIM) / 4;
    int total4 = ns4 + nv4;
    for (int t = blockIdx.x * blockDim.x + threadIdx.x; t < total4;
         t += gridDim.x * blockDim.x) {
        float4 val = (t < ns4) ? ((const float4*)s)[t]
                               : ((const float4*)v)[t - ns4];
        ((float4*)out)[t] = val;
    }
}

// ---------------- SGEMM: C = A[M,K] @ B[K,N] + bias, optional SiLU ----------
// BM=128, BN=64, BK=16, TM=8, TN=4, 256 threads, FFMA2 inner loop.
template <bool SILU>
__global__ __launch_bounds__(256) void sgemm_kernel(
    const float* __restrict__ A, const float* __restrict__ B,
    const float* __restrict__ bias, float* __restrict__ C,
    int M, int N, int K) {
    __shared__ float As[16][132];  // transposed, padded
    __shared__ float Bs[16][64];

    int tid = threadIdx.x;
    int tx = tid % 16, ty = tid / 16;  // ty 0..15 -> 8 rows each
    int bRow = blockIdx.y * 128, bCol = blockIdx.x * 64;
    int bRowL = tid / 16, bColL = (tid % 16) * 4;

    unsigned long long accp[8][2];
#pragma unroll
    for (int i = 0; i < 8; i++) {
        accp[i][0] = 0ULL;
        accp[i][1] = 0ULL;
    }

    for (int kt = 0; kt < K; kt += 16) {
        // A tile: 128 rows x 16 cols = 512 float4; 2 per thread
#pragma unroll
        for (int l = 0; l < 2; l++) {
            int idx = tid + l * 256;
            int row = idx >> 2, c4 = (idx & 3) * 4;
            float4 a = make_float4(0.f, 0.f, 0.f, 0.f);
            int gRow = bRow + row;
            if (gRow < M) a = *(const float4*)(A + (size_t)gRow * K + kt + c4);
            As[c4 + 0][row] = a.x;
            As[c4 + 1][row] = a.y;
            As[c4 + 2][row] = a.z;
            As[c4 + 3][row] = a.w;
        }
        float4 b = *(const float4*)(B + (size_t)(kt + bRowL) * N + bCol + bColL);
        *(float4*)&Bs[bRowL][bColL] = b;
        __syncthreads();

#pragma unroll
        for (int k = 0; k < 16; ++k) {
            float4 bn = *(float4*)&Bs[k][tx * 4];
            unsigned long long pb0 = pack2(bn.x, bn.y);
            unsigned long long pb1 = pack2(bn.z, bn.w);
#pragma unroll
            for (int i = 0; i < 8; i++) {
                float rm = As[k][ty * 8 + i];
                unsigned long long rd = pack2(rm, rm);
                accp[i][0] = fma2(rd, pb0, accp[i][0]);
                accp[i][1] = fma2(rd, pb1, accp[i][1]);
            }
        }
        __syncthreads();
    }

#pragma unroll
    for (int i = 0; i < 8; i++) {
        int r = bRow + ty * 8 + i;
        if (r >= M) continue;
        float2 p0 = unpack2(accp[i][0]);
        float2 p1 = unpack2(accp[i][1]);
        float vals[4] = {p0.x, p0.y, p1.x, p1.y};
#pragma unroll
        for (int j = 0; j < 4; j++) {
            int c = bCol + tx * 4 + j;
            float val = vals[j] + bias[c];
            if (SILU) val = val / (1.0f + expf(-val));
            C[(size_t)r * N + c] = val;
        }
    }
}

// ---------------- fused edge kernel (pipelined tiles) ----------------------
// 512 threads = 4 eslots x 128 features; 8 edges/eslot per 32-edge tile.
// Wr resident in SMEM as two float4 arrays; mainloop FFMA2 with native
// chunk-pair LDS. Tile staging (rcomb + metadata) is double-buffered and
// issued for tile t+grid right after the single loop-top barrier, so its
// LDG latency hides under tile t's ~8k-cycle mainloop. ONE barrier/tile.
__global__ __launch_bounds__(512, 1) void edge_kernel(
    const float* __restrict__ re1, const float* __restrict__ re2,
    const float* __restrict__ re3, const float* __restrict__ fc1,
    const float* __restrict__ fc2, const float* __restrict__ fc3,
    const float* __restrict__ uv1, const float* __restrict__ uv2,
    const float* __restrict__ uv3, const int* __restrict__ eidx,
    const float* __restrict__ Wr, const float* __restrict__ br,
    const float* __restrict__ v, float* __restrict__ out) {
    extern __shared__ float smem[];
    float4* wrA = (float4*)smem;          // [32*128] chunks 0..3
    float4* wrB = wrA + NRBD * FDIM;      // [32*128] chunks 4..7
    float4* rc4 = wrB + NRBD * FDIM;      // [2][32 edges][8]
    float* uvs = (float*)(rc4 + 2 * 256); // [2][32*9]
    float* fcs = uvs + 2 * 288;           // [2][32]
    int* iis = (int*)(fcs + 2 * 32);      // [2][32]
    int* jjs = iis + 2 * 32;              // [2][32]

    int tid = threadIdx.x;

    // one-time Wr load into transposed/split SMEM layout
    for (int idx = tid; idx < NRBD * PHI_DIM; idx += 512) {
        int k = idx >> 10;
        int col = idx & 1023;
        int c = col >> 7, ffi = col & 127;
        float val = Wr[idx];
        float* dst = (c < 4) ? (float*)&wrA[k * FDIM + ffi]
                             : (float*)&wrB[k * FDIM + ffi];
        dst[c & 3] = val;
    }

    int ff = tid & 127;
    int eslot = tid >> 7;

    float brc[8];
#pragma unroll
    for (int c = 0; c < 8; c++) brc[c] = br[c * FDIM + ff];

    float* out_s = out;
    float* out_v = out + (size_t)N_NODES * FDIM;

    const int numTiles = N_EDGES / 32;

    // ---- staging lambda (writes one buffer, no sync) ----
    auto stage = [&](int buf, int tileId) {
        int eBase = tileId * 32;
        if (tid < 256) {
            int t = tid;
            int e = t >> 3;
            int ge = eBase + e;
            float c1 = fc1[ge], c2 = fc2[ge], c3 = fc3[ge];
            float4 a = ((const float4*)re1)[ge * 8 + (t & 7)];
            float4 b = ((const float4*)re2)[ge * 8 + (t & 7)];
            float4 c = ((const float4*)re3)[ge * 8 + (t & 7)];
            float4 r;
            r.x = a.x * c1 + b.x * c2 + c.x * c3;
            r.y = a.y * c1 + b.y * c2 + c.y * c3;
            r.z = a.z * c1 + b.z * c2 + c.z * c3;
            r.w = a.w * c1 + b.w * c2 + c.w * c3;
            rc4[buf * 256 + t] = r;
        } else if (tid < 288) {
            int le = tid - 256;
            int ge = eBase + le;
            iis[buf * 32 + le] = eidx[ge];
            jjs[buf * 32 + le] = eidx[N_EDGES + ge];
            fcs[buf * 32 + le] = fc1[ge] + fc2[ge] + fc3[ge];
#pragma unroll
            for (int d = 0; d < 3; d++) {
                uvs[buf * 288 + le * 9 + d] = uv1[ge * 3 + d];
                uvs[buf * 288 + le * 9 + 3 + d] = uv2[ge * 3 + d];
                uvs[buf * 288 + le * 9 + 6 + d] = uv3[ge * 3 + d];
            }
        }
    };

    // prologue: stage first tile into buffer 0
    stage(0, blockIdx.x);
    int cur = 0;

    for (int tile = blockIdx.x; tile < numTiles; tile += gridDim.x) {
        __syncthreads();  // staging of buffer `cur` complete; prev reads done

        // stage next tile into the other buffer (LDG latency hides under
        // this tile's mainloop)
        int nxt = tile + gridDim.x;
        if (nxt < numTiles) stage(1 - cur, nxt);

        const float4* rcb = rc4 + cur * 256;
        const float* fcb = fcs + cur * 32;
        const float* uvb = uvs + cur * 288;
        const int* iib = iis + cur * 32;
        const int* jjb = jjs + cur * 32;

        // W accumulators: 8 edges x 4 chunk-pairs, packed f32x2
        unsigned long long accp[8][4];
#pragma unroll
        for (int e = 0; e < 8; e++) {
            float fs = fcb[eslot * 8 + e];
            accp[e][0] = pack2(fs * brc[0], fs * brc[1]);
            accp[e][1] = pack2(fs * brc[2], fs * brc[3]);
            accp[e][2] = pack2(fs * brc[4], fs * brc[5]);
            accp[e][3] = pack2(fs * brc[6], fs * brc[7]);
        }

#pragma unroll
        for (int kk = 0; kk < 8; ++kk) {
            float4 r[8];
#pragma unroll
            for (int e = 0; e < 8; e++) r[e] = rcb[(eslot * 8 + e) * 8 + kk];
#pragma unroll
            for (int d = 0; d < 4; ++d) {
                int k = kk * 4 + d;
                // chunk-pairs load natively as u64 halves of the float4
                ulonglong2 wa = *(const ulonglong2*)&wrA[k * FDIM + ff];
                ulonglong2 wb = *(const ulonglong2*)&wrB[k * FDIM + ff];
#pragma unroll
                for (int e = 0; e < 8; e++) {
                    float rv = (d == 0) ? r[e].x
                             : (d == 1) ? r[e].y
                             : (d == 2) ? r[e].z
                                        : r[e].w;
                    unsigned long long rp = pack2(rv, rv);
                    accp[e][0] = fma2(rp, wa.x, accp[e][0]);
                    accp[e][1] = fma2(rp, wa.y, accp[e][1]);
                    accp[e][2] = fma2(rp, wb.x, accp[e][2]);
                    accp[e][3] = fma2(rp, wb.y, accp[e][3]);
                }
            }
        }

        // epilogue: pairs of edges; hoist all global loads before the math
#pragma unroll
        for (int pp = 0; pp < 4; pp++) {
            int le0 = eslot * 8 + 2 * pp;
            int le1 = le0 + 1;
            int i0 = iib[le0], j0 = jjb[le0];
            int i1 = iib[le1], j1 = jjb[le1];

            const float* pj0 = g_phi + (size_t)j0 * PHI_DIM + ff;
            const float* pj1 = g_phi + (size_t)j1 * PHI_DIM + ff;
            const float* vj0 = v + (size_t)j0 * (3 * FDIM) + ff;
            const float* vj1 = v + (size_t)j1 * (3 * FDIM) + ff;

            float ph0[8], ph1[8];
#pragma unroll
            for (int c = 0; c < 8; c++) ph0[c] = __ldg(pj0 + c * FDIM);
#pragma unroll
            for (int c = 0; c < 8; c++) ph1[c] = __ldg(pj1 + c * FDIM);
            float va0 = __ldg(vj0), vb0 = __ldg(vj0 + 128), vc0 = __ldg(vj0 + 256);
            float va1 = __ldg(vj1), vb1 = __ldg(vj1 + 128), vc1 = __ldg(vj1 + 256);

#pragma unroll
            for (int q = 0; q < 2; q++) {
                int le = q ? le1 : le0;
                int i = q ? i1 : i0;
                const float* ph = q ? ph1 : ph0;
                float v0 = q ? va1 : va0;
                float v1 = q ? vb1 : vb0;
                float v2 = q ? vc1 : vc0;
                int eloc = le - eslot * 8;
                float2 p0 = unpack2(accp[eloc][0]);
                float2 p1 = unpack2(accp[eloc][1]);
                float2 p2 = unpack2(accp[eloc][2]);
                float2 p3 = unpack2(accp[eloc][3]);
                float x0 = p0.x * ph[0];
                float x1 = p0.y * ph[1];
                float x2 = p1.x * ph[2];
                float x3 = p1.y * ph[3];
                float x4 = p2.x * ph[4];
                float x5 = p2.y * ph[5];
                float x6 = p3.x * ph[6];
                float x7 = p3.y * ph[7];

                float u1x = uvb[le * 9 + 0], u1y = uvb[le * 9 + 1],
                      u1z = uvb[le * 9 + 2];
                float u2x = uvb[le * 9 + 3], u2y = uvb[le * 9 + 4],
                      u2z = uvb[le * 9 + 5];
                float u3x = uvb[le * 9 + 6], u3y = uvb[le * 9 + 7],
                      u3z = uvb[le * 9 + 8];

                // cross(vj,u) = (v1*uz - v2*uy, v2*ux - v0*uz, v0*uy - v1*ux)
                float xv0 = v0 * x1 + x2 * u1x + x3 * u2x + x4 * u3x +
                            x5 * (v1 * u1z - v2 * u1y) +
                            x6 * (v1 * u2z - v2 * u2y) +
                            x7 * (v1 * u3z - v2 * u3y);
                float xv1 = v1 * x1 + x2 * u1y + x3 * u2y + x4 * u3y +
                            x5 * (v2 * u1x - v0 * u1z) +
                            x6 * (v2 * u2x - v0 * u2z) +
                            x7 * (v2 * u3x - v0 * u3z);
                float xv2 = v2 * x1 + x2 * u1z + x3 * u2z + x4 * u3z +
                            x5 * (v0 * u1y - v1 * u1x) +
                            x6 * (v0 * u2y - v1 * u2x) +
                            x7 * (v0 * u3y - v1 * u3x);

                atomicAdd(out_s + (size_t)i * FDIM + ff, x0);
                float* ov = out_v + (size_t)i * (3 * FDIM) + ff;
                atomicAdd(ov, xv0);
                atomicAdd(ov + 128, xv1);
                atomicAdd(ov + 256, xv2);
            }
        }
        cur ^= 1;
    }
}

// ---------------- host ----------------
extern "C" void kernel_launch(void* const* d_in, const int* in_sizes, int n_in,
                              void* d_out, int out_size) {
    const float* s = (const float*)d_in[0];
    const float* v = (const float*)d_in[1];
    const float* re1 = (const float*)d_in[2];
    const float* re2 = (const float*)d_in[3];
    const float* re3 = (const float*)d_in[4];
    const float* fc1 = (const float*)d_in[5];
    const float* fc2 = (const float*)d_in[6];
    const float* fc3 = (const float*)d_in[7];
    const float* uv1 = (const float*)d_in[8];
    const float* uv2 = (const float*)d_in[9];
    const float* uv3 = (const float*)d_in[10];
    const int* eidx = (const int*)d_in[11];
    const float* W1 = (const float*)d_in[12];
    const float* b1 = (const float*)d_in[13];
    const float* W2 = (const float*)d_in[14];
    const float* b2 = (const float*)d_in[15];
    const float* Wr = (const float*)d_in[16];
    const float* br = (const float*)d_in[17];
    float* out = (float*)d_out;

    float *hptr, *phiptr;
    cudaGetSymbolAddress((void**)&hptr, g_h);
    cudaGetSymbolAddress((void**)&phiptr, g_phi);

    init_out_kernel<<<256, 256>>>(s, v, out);

    dim3 g1(FDIM / 64, (N_NODES + 127) / 128);
    sgemm_kernel<true><<<g1, 256>>>(s, W1, b1, hptr, N_NODES, FDIM, FDIM);

    dim3 g2(PHI_DIM / 64, (N_NODES + 127) / 128);
    sgemm_kernel<false><<<g2, 256>>>(hptr, W2, b2, phiptr, N_NODES, PHI_DIM, FDIM);

    int smem_bytes = (NRBD * FDIM * 2 + 2 * 256) * (int)sizeof(float4) +
                     (2 * 288 + 2 * 32) * (int)sizeof(float) +
                     2 * 2 * 32 * (int)sizeof(int);
    cudaFuncSetAttribute(edge_kernel,
                         cudaFuncAttributeMaxDynamicSharedMemorySize, smem_bytes);
    edge_kernel<<<148, 512, smem_bytes>>>(re1, re2, re3, fc1, fc2, fc3, uv1, uv2,
                                          uv3, eidx, Wr, br, v, out);
}